// round 6
// baseline (speedup 1.0000x reference)
#include <cuda_runtime.h>
#include <cstdint>

// ---------------- constants ----------------
#define HN     256
#define WN     256
#define HPAD   258
#define WPAD   258
#define NPTS   100000
#define BATCH  4
#define TOTPTS 400000
#define PLANE_PAD (HPAD*WPAD)                        // 66564
#define GRID_ELEMS ((size_t)BATCH*64*HPAD*WPAD)      // 17,040,384

// ---------------- device scratch ----------------
__device__ float g_bev[GRID_ELEMS];
__device__ float g_tmp[GRID_ELEMS];   // halo stays .bss-zero; interior rewritten each run
__device__ float g_w1t[64*134];       // [co][134], k<131 valid, BN-folded (conflict-free stride)
__device__ float g_w2t[64*70];        // [co][70],  c<64 valid
__device__ float g_wc1[9*64*64];      // [tap][ci][co], BN-folded
__device__ float g_wc2[9*64*64];
__device__ float g_fb1[64];
__device__ float g_cb1[64];
__device__ float g_cb2[64];

// ---------------- f32x2 helpers ----------------
#define FMA2(d, a, b) asm("fma.rn.f32x2 %0, %1, %2, %0;" : "+l"(d) : "l"(a), "l"(b))
#define UNPACK2(lo, hi, v) asm("mov.b64 {%0, %1}, %2;" : "=f"(lo), "=f"(hi) : "l"(v))
__device__ __forceinline__ unsigned long long PACK2(float x, float y){
    unsigned long long r;
    asm("mov.b64 %0, {%1, %2};" : "=l"(r) : "f"(x), "f"(y));
    return r;
}

// ---------------- prep: fold BN into weights, transpose layouts ----------------
__global__ void prep_kernel(
    const float* __restrict__ w1, const float* __restrict__ b1,
    const float* __restrict__ g1, const float* __restrict__ be1,
    const float* __restrict__ m1, const float* __restrict__ v1,
    const float* __restrict__ w2,
    const float* __restrict__ cw1, const float* __restrict__ cb1,
    const float* __restrict__ cg1, const float* __restrict__ cbe1,
    const float* __restrict__ cm1, const float* __restrict__ cv1,
    const float* __restrict__ cw2, const float* __restrict__ cb2,
    const float* __restrict__ cg2, const float* __restrict__ cbe2,
    const float* __restrict__ cm2, const float* __restrict__ cv2)
{
    int idx = blockIdx.x*blockDim.x + threadIdx.x;
    if (idx < 64*134){
        int co = idx/134, k = idx - co*134;
        float s = g1[co]*rsqrtf(v1[co]+1e-5f);
        g_w1t[idx] = (k < 131) ? w1[k*64+co]*s : 0.f;
        return;
    }
    idx -= 64*134;
    if (idx < 64*70){
        int co = idx/70, c = idx - co*70;
        g_w2t[idx] = (c < 64) ? w2[c*64+co] : 0.f;
        return;
    }
    idx -= 64*70;
    if (idx < 9*64*64){
        int co = idx & 63, ci = (idx>>6)&63, t = idx>>12;
        float s = cg1[co]*rsqrtf(cv1[co]+1e-5f);
        g_wc1[idx] = cw1[(co*64+ci)*9 + t]*s;
        return;
    }
    idx -= 9*64*64;
    if (idx < 9*64*64){
        int co = idx & 63, ci = (idx>>6)&63, t = idx>>12;
        float s = cg2[co]*rsqrtf(cv2[co]+1e-5f);
        g_wc2[idx] = cw2[(co*64+ci)*9 + t]*s;
        return;
    }
    idx -= 9*64*64;
    if (idx < 64){
        float s = g1[idx]*rsqrtf(v1[idx]+1e-5f);
        g_fb1[idx] = (b1[idx]-m1[idx])*s + be1[idx];
        return;
    }
    idx -= 64;
    if (idx < 64){
        float s = cg1[idx]*rsqrtf(cv1[idx]+1e-5f);
        g_cb1[idx] = (cb1[idx]-cm1[idx])*s + cbe1[idx];
        return;
    }
    idx -= 64;
    if (idx < 64){
        float s = cg2[idx]*rsqrtf(cv2[idx]+1e-5f);
        g_cb2[idx] = (cb2[idx]-cm2[idx])*s + cbe2[idx];
    }
}

// ---------------- zero BEV grid ----------------
__global__ void zero_kernel(){
    size_t i = (size_t)blockIdx.x*blockDim.x + threadIdx.x;
    size_t n4 = GRID_ELEMS/4;
    if (i < n4) ((float4*)g_bev)[i] = make_float4(0.f,0.f,0.f,0.f);
}

// ---------------- point MLP + scatter-max ----------------
// 128 threads: cg = tid&15 -> co {cg, cg+16, cg+32, cg+48}; pg = tid>>4 -> 8 pts each.
#define MLP_ITERS 4
#define NCHUNKS   6250
#define MLP_SMEM_FLOATS (64*134 + 64*70 + 64*132 + 64*68 + 64 + 64 + 64)

__global__ __launch_bounds__(128, 2)
void mlp_scatter_kernel(const float* __restrict__ points,
                        const float* __restrict__ features,
                        const float* __restrict__ b2)
{
    extern __shared__ float sm[];
    float* s_w1t  = sm;                  // [64][134]
    float* s_w2t  = s_w1t + 64*134;      // [64][70]
    float* s_comb = s_w2t + 64*70;       // [64][132]
    float* s_h    = s_comb + 64*132;     // [64][68]
    float* s_fb1  = s_h + 64*68;         // 64
    float* s_b2   = s_fb1 + 64;          // 64
    int*   s_info = (int*)(s_b2 + 64);   // 64

    int tid = threadIdx.x;
    int cg = tid & 15;
    int pg = tid >> 4;                   // 0..7

    for (int i = tid; i < 64*134; i += 128) s_w1t[i] = g_w1t[i];
    for (int i = tid; i < 64*70;  i += 128) s_w2t[i] = g_w2t[i];
    if (tid < 64){ s_fb1[tid] = g_fb1[tid]; s_b2[tid] = b2[tid]; }
    __syncthreads();

    const float* w1p0 = s_w1t + cg*134;
    const float* w1p1 = s_w1t + (cg+16)*134;
    const float* w1p2 = s_w1t + (cg+32)*134;
    const float* w1p3 = s_w1t + (cg+48)*134;
    const float* w2p0 = s_w2t + cg*70;
    const float* w2p1 = s_w2t + (cg+16)*70;
    const float* w2p2 = s_w2t + (cg+32)*70;
    const float* w2p3 = s_w2t + (cg+48)*70;

    for (int it = 0; it < MLP_ITERS; ++it){
        int chunk = blockIdx.x*MLP_ITERS + it;
        if (chunk >= NCHUNKS) break;                 // uniform per block
        int g0 = chunk * 64;

        // ---- stage 64 points: 2048 float4 via 128 threads ----
        {
            const float4* fsrc = (const float4*)(features + (size_t)g0*128);
            #pragma unroll
            for (int i = 0; i < 16; ++i){
                int idx = tid + i*128;
                int pt = idx >> 5, c4 = idx & 31;
                ((float4*)&s_comb[pt*132])[c4] = fsrc[pt*32 + c4];
            }
            if (tid < 64){
                int g = g0 + tid;
                float x = points[(size_t)g*3+0];
                float y = points[(size_t)g*3+1];
                float z = points[(size_t)g*3+2];
                bool valid = (x >= -50.f) && (x < 50.f) && (y >= -50.f) &&
                             (y < 50.f) && (z >= -3.f) && (z < 5.f);
                s_comb[tid*132+128] = __fdiv_rn(x + 50.f, 100.f);
                s_comb[tid*132+129] = __fdiv_rn(y + 50.f, 100.f);
                s_comb[tid*132+130] = __fdiv_rn(z + 3.f, 8.f);
                s_comb[tid*132+131] = 0.f;
                int info = -1;
                if (valid){
                    int col = (int)__fdiv_rn(x + 50.f, 0.390625f);
                    int row = (int)__fdiv_rn(y + 50.f, 0.390625f);
                    col = min(max(col,0),255); row = min(max(row,0),255);
                    int b = g / NPTS;
                    info = (b<<18) | (row<<9) | col;
                }
                s_info[tid] = info;
            }
        }
        __syncthreads();

        // ---- layer 1: 8 pts x 4 co over K=132 ----
        {
            unsigned long long acc[8][4];
            #pragma unroll
            for (int i = 0; i < 8; ++i)
                #pragma unroll
                for (int j = 0; j < 4; ++j) acc[i][j] = 0ULL;
            const float* xbase = s_comb + (pg*8)*132;
            #pragma unroll 3
            for (int k4 = 0; k4 < 33; ++k4){
                unsigned long long w0a = *(const unsigned long long*)(w1p0 + k4*4);
                unsigned long long w0b = *(const unsigned long long*)(w1p0 + k4*4 + 2);
                unsigned long long w1a = *(const unsigned long long*)(w1p1 + k4*4);
                unsigned long long w1b = *(const unsigned long long*)(w1p1 + k4*4 + 2);
                unsigned long long w2a = *(const unsigned long long*)(w1p2 + k4*4);
                unsigned long long w2b = *(const unsigned long long*)(w1p2 + k4*4 + 2);
                unsigned long long w3a = *(const unsigned long long*)(w1p3 + k4*4);
                unsigned long long w3b = *(const unsigned long long*)(w1p3 + k4*4 + 2);
                #pragma unroll
                for (int i = 0; i < 8; ++i){
                    ulonglong2 xv = *(const ulonglong2*)(xbase + i*132 + k4*4);
                    FMA2(acc[i][0], xv.x, w0a); FMA2(acc[i][0], xv.y, w0b);
                    FMA2(acc[i][1], xv.x, w1a); FMA2(acc[i][1], xv.y, w1b);
                    FMA2(acc[i][2], xv.x, w2a); FMA2(acc[i][2], xv.y, w2b);
                    FMA2(acc[i][3], xv.x, w3a); FMA2(acc[i][3], xv.y, w3b);
                }
            }
            float fb[4] = { s_fb1[cg], s_fb1[cg+16], s_fb1[cg+32], s_fb1[cg+48] };
            #pragma unroll
            for (int i = 0; i < 8; ++i){
                #pragma unroll
                for (int j = 0; j < 4; ++j){
                    float lo, hi;
                    UNPACK2(lo, hi, acc[i][j]);
                    s_h[(pg*8+i)*68 + cg + 16*j] = fmaxf(lo + hi + fb[j], 0.f);
                }
            }
        }
        __syncthreads();

        // ---- layer 2 + scatter ----
        {
            unsigned long long acc[8][4];
            #pragma unroll
            for (int i = 0; i < 8; ++i)
                #pragma unroll
                for (int j = 0; j < 4; ++j) acc[i][j] = 0ULL;
            const float* xbase = s_h + (pg*8)*68;
            #pragma unroll 4
            for (int k4 = 0; k4 < 16; ++k4){
                unsigned long long w0a = *(const unsigned long long*)(w2p0 + k4*4);
                unsigned long long w0b = *(const unsigned long long*)(w2p0 + k4*4 + 2);
                unsigned long long w1a = *(const unsigned long long*)(w2p1 + k4*4);
                unsigned long long w1b = *(const unsigned long long*)(w2p1 + k4*4 + 2);
                unsigned long long w2a = *(const unsigned long long*)(w2p2 + k4*4);
                unsigned long long w2b = *(const unsigned long long*)(w2p2 + k4*4 + 2);
                unsigned long long w3a = *(const unsigned long long*)(w2p3 + k4*4);
                unsigned long long w3b = *(const unsigned long long*)(w2p3 + k4*4 + 2);
                #pragma unroll
                for (int i = 0; i < 8; ++i){
                    ulonglong2 xv = *(const ulonglong2*)(xbase + i*68 + k4*4);
                    FMA2(acc[i][0], xv.x, w0a); FMA2(acc[i][0], xv.y, w0b);
                    FMA2(acc[i][1], xv.x, w1a); FMA2(acc[i][1], xv.y, w1b);
                    FMA2(acc[i][2], xv.x, w2a); FMA2(acc[i][2], xv.y, w2b);
                    FMA2(acc[i][3], xv.x, w3a); FMA2(acc[i][3], xv.y, w3b);
                }
            }
            float bb[4] = { s_b2[cg], s_b2[cg+16], s_b2[cg+32], s_b2[cg+48] };
            #pragma unroll
            for (int i = 0; i < 8; ++i){
                int info = s_info[pg*8+i];
                if (info < 0) continue;
                int b   = info >> 18;
                int row = (info >> 9) & 511;
                int colc = info & 511;
                size_t obase = ((size_t)(b*64 + cg)*HPAD + row + 1)*WPAD + colc + 1;
                #pragma unroll
                for (int j = 0; j < 4; ++j){
                    float lo, hi;
                    UNPACK2(lo, hi, acc[i][j]);
                    float v = lo + hi + bb[j];
                    if (v > 0.f)
                        atomicMax((unsigned int*)&g_bev[obase + (size_t)(16*j)*PLANE_PAD],
                                  __float_as_uint(v));
                }
            }
        }
        __syncthreads();
    }
}

// ---------------- 3x3 conv (BN-folded) + ReLU, deep register blocking ----------------
// 256 threads: tx=tid&31, q=tid>>5 (8 warps), ty=q&1 (row half), cgq=q>>1 (0..3).
// Thread: 4 pixels (rows 4ty..4ty+3) x 16 co. Tile 8x32. ci chunks of 16.
#define CONV_SMEM_FLOATS (16*10*34 + 9*16*64 + 64)   // 5440+9216+64=14720 (58.9KB)

template<bool PADOUT>
__global__ __launch_bounds__(256, 2)
void conv_kernel(const float* __restrict__ in, const float* __restrict__ wfold,
                 const float* __restrict__ bias, float* __restrict__ out)
{
    extern __shared__ float sm[];
    float* s_in   = sm;                 // [16 ci][10 rows][34]
    float* s_w    = s_in + 16*10*34;    // [9][16][64]
    float* s_bias = s_w + 9*16*64;      // 64

    int tid = threadIdx.x;
    int tx = tid & 31;
    int q  = tid >> 5;
    int ty = q & 1;
    int cgq = q >> 1;                   // 0..3
    int b = blockIdx.z;
    int row0 = blockIdx.y * 8;          // output row base (== padded top input row)
    int col0 = blockIdx.x * 32;         // output col base (== padded left input col)

    if (tid < 64) s_bias[tid] = bias[tid];

    unsigned long long acc[4][8];
    #pragma unroll
    for (int r = 0; r < 4; ++r)
        #pragma unroll
        for (int j = 0; j < 8; ++j) acc[r][j] = 0ULL;

    const float* inb = in + (size_t)b*64*PLANE_PAD;

    #pragma unroll 1
    for (int ch = 0; ch < 4; ++ch){
        __syncthreads();
        // input chunk: 16 ci x 10 rows x 34 cols (warp per (ci,row) segment)
        #pragma unroll 1
        for (int s = q; s < 160; s += 8){
            int ci = s / 10, r = s - ci*10;
            const float* src = inb + ((size_t)(ch*16+ci)*HPAD + row0 + r)*WPAD + col0;
            float* dst = s_in + ci*340 + r*34;
            dst[tx] = src[tx];
            if (tx < 2) dst[32+tx] = src[32+tx];
        }
        // weight chunk [9][16][64]
        {
            const float4* gw = (const float4*)wfold;
            float4* sw = (float4*)s_w;
            #pragma unroll 1
            for (int i4 = tid; i4 < 2304; i4 += 256){
                int t = i4 >> 8;
                int rem = i4 & 255;
                sw[i4] = gw[t*1024 + ch*256 + rem];
            }
        }
        __syncthreads();

        #pragma unroll 1
        for (int ci = 0; ci < 16; ++ci){
            const float* xb = s_in + ci*340 + (4*ty)*34 + tx;
            float xr[6][3];
            #pragma unroll
            for (int rr = 0; rr < 6; ++rr)
                #pragma unroll
                for (int cc = 0; cc < 3; ++cc)
                    xr[rr][cc] = xb[rr*34 + cc];

            #pragma unroll
            for (int t = 0; t < 9; ++t){
                const int dh = t/3, dw = t - dh*3;
                unsigned long long xx0 = PACK2(xr[dh  ][dw], xr[dh  ][dw]);
                unsigned long long xx1 = PACK2(xr[dh+1][dw], xr[dh+1][dw]);
                unsigned long long xx2 = PACK2(xr[dh+2][dw], xr[dh+2][dw]);
                unsigned long long xx3 = PACK2(xr[dh+3][dw], xr[dh+3][dw]);
                const ulonglong2* wp =
                    (const ulonglong2*)(s_w + t*1024 + ci*64 + cgq*16);
                #pragma unroll
                for (int jj = 0; jj < 4; ++jj){
                    ulonglong2 wv = wp[jj];
                    FMA2(acc[0][2*jj],   xx0, wv.x);
                    FMA2(acc[0][2*jj+1], xx0, wv.y);
                    FMA2(acc[1][2*jj],   xx1, wv.x);
                    FMA2(acc[1][2*jj+1], xx1, wv.y);
                    FMA2(acc[2][2*jj],   xx2, wv.x);
                    FMA2(acc[2][2*jj+1], xx2, wv.y);
                    FMA2(acc[3][2*jj],   xx3, wv.x);
                    FMA2(acc[3][2*jj+1], xx3, wv.y);
                }
            }
        }
    }

    // ---- store: 4 px x 16 co, per-channel coalesced ----
    int h0 = row0 + 4*ty;
    int w  = col0 + tx;
    #pragma unroll
    for (int m = 0; m < 8; ++m){
        int co = cgq*16 + 2*m;
        float bia = s_bias[co], bib = s_bias[co+1];
        #pragma unroll
        for (int r = 0; r < 4; ++r){
            float lo, hi;
            UNPACK2(lo, hi, acc[r][m]);
            float v0 = fmaxf(lo + bia, 0.f);
            float v1 = fmaxf(hi + bib, 0.f);
            if (PADOUT){
                size_t o0 = ((size_t)(b*64+co)*HPAD + h0+r+1)*WPAD + (w+1);
                out[o0] = v0;
                out[o0 + (size_t)PLANE_PAD] = v1;
            } else {
                size_t o0 = ((size_t)(b*64+co)*HN + h0+r)*WN + w;
                out[o0] = v0;
                out[o0 + (size_t)HN*WN] = v1;
            }
        }
    }
}

// ---------------- launch ----------------
extern "C" void kernel_launch(void* const* d_in, const int* in_sizes, int n_in,
                              void* d_out, int out_size)
{
    const float* points   = (const float*)d_in[0];
    const float* features = (const float*)d_in[1];
    const float* w1   = (const float*)d_in[2];
    const float* b1   = (const float*)d_in[3];
    const float* g1   = (const float*)d_in[4];
    const float* be1  = (const float*)d_in[5];
    const float* m1   = (const float*)d_in[6];
    const float* v1   = (const float*)d_in[7];
    const float* w2   = (const float*)d_in[8];
    const float* b2   = (const float*)d_in[9];
    const float* cw1  = (const float*)d_in[10];
    const float* cb1  = (const float*)d_in[11];
    const float* cg1  = (const float*)d_in[12];
    const float* cbe1 = (const float*)d_in[13];
    const float* cm1  = (const float*)d_in[14];
    const float* cv1  = (const float*)d_in[15];
    const float* cw2  = (const float*)d_in[16];
    const float* cb2  = (const float*)d_in[17];
    const float* cg2  = (const float*)d_in[18];
    const float* cbe2 = (const float*)d_in[19];
    const float* cm2  = (const float*)d_in[20];
    const float* cv2  = (const float*)d_in[21];
    float* out = (float*)d_out;

    void *p_bev, *p_tmp, *p_wc1, *p_wc2, *p_cb1, *p_cb2;
    cudaGetSymbolAddress(&p_bev, g_bev);
    cudaGetSymbolAddress(&p_tmp, g_tmp);
    cudaGetSymbolAddress(&p_wc1, g_wc1);
    cudaGetSymbolAddress(&p_wc2, g_wc2);
    cudaGetSymbolAddress(&p_cb1, g_cb1);
    cudaGetSymbolAddress(&p_cb2, g_cb2);

    int mlp_smem  = MLP_SMEM_FLOATS * 4;
    int conv_smem = CONV_SMEM_FLOATS * 4;
    cudaFuncSetAttribute(mlp_scatter_kernel,
        cudaFuncAttributeMaxDynamicSharedMemorySize, mlp_smem);
    cudaFuncSetAttribute(conv_kernel<true>,
        cudaFuncAttributeMaxDynamicSharedMemorySize, conv_smem);
    cudaFuncSetAttribute(conv_kernel<false>,
        cudaFuncAttributeMaxDynamicSharedMemorySize, conv_smem);

    // 1) fold weights
    int prep_total = 64*134 + 64*70 + 2*9*64*64 + 3*64;
    prep_kernel<<<(prep_total+255)/256, 256>>>(
        w1,b1,g1,be1,m1,v1, w2,
        cw1,cb1,cg1,cbe1,cm1,cv1,
        cw2,cb2,cg2,cbe2,cm2,cv2);

    // 2) zero BEV grid
    size_t n4 = GRID_ELEMS/4;
    zero_kernel<<<(int)((n4+255)/256), 256>>>();

    // 3) point MLP + scatter-max
    int mlp_blocks = (NCHUNKS + MLP_ITERS - 1) / MLP_ITERS;
    mlp_scatter_kernel<<<mlp_blocks, 128, mlp_smem>>>(points, features, b2);

    // 4) conv1: g_bev -> g_tmp (padded)
    dim3 cgrid(WN/32, HN/8, BATCH);
    conv_kernel<true><<<cgrid, 256, conv_smem>>>(
        (const float*)p_bev, (const float*)p_wc1, (const float*)p_cb1,
        (float*)p_tmp);

    // 5) conv2: g_tmp -> d_out (NCHW)
    conv_kernel<false><<<cgrid, 256, conv_smem>>>(
        (const float*)p_tmp, (const float*)p_wc2, (const float*)p_cb2,
        out);
}

// round 7
// speedup vs baseline: 1.8950x; 1.8950x over previous
#include <cuda_runtime.h>
#include <cuda_bf16.h>
#include <cstdint>

// ---------------- constants ----------------
#define HN     256
#define WN     256
#define HPAD   258
#define WPAD   258
#define NPTS   100000
#define BATCH  4
#define TOTPTS 400000
#define PLANE_PAD (HPAD*WPAD)                        // 66564
#define GRID_ELEMS ((size_t)BATCH*64*HPAD*WPAD)      // 17,040,384

// ---------------- device scratch ----------------
__device__ float g_bev[GRID_ELEMS];                  // fp32 NCHW padded (scatter target)
__device__ __nv_bfloat16 g_c1h[GRID_ELEMS];          // conv1 input NHWC padded, hi
__device__ __nv_bfloat16 g_c1l[GRID_ELEMS];          // lo
__device__ __nv_bfloat16 g_c2h[GRID_ELEMS];          // conv2 input NHWC padded, hi
__device__ __nv_bfloat16 g_c2l[GRID_ELEMS];          // lo
__device__ __nv_bfloat16 g_cw1h[9*64*64];            // [tap][co][ci] bf16 hi, BN-folded
__device__ __nv_bfloat16 g_cw1l[9*64*64];
__device__ __nv_bfloat16 g_cw2h[9*64*64];
__device__ __nv_bfloat16 g_cw2l[9*64*64];
__device__ float g_w1t[64*134];       // MLP L1 [co][134], BN-folded
__device__ float g_w2t[64*70];        // MLP L2 [co][70]
__device__ float g_fb1[64];
__device__ float g_cb1[64];
__device__ float g_cb2[64];

// ---------------- f32x2 helpers (MLP) ----------------
#define FMA2(d, a, b) asm("fma.rn.f32x2 %0, %1, %2, %0;" : "+l"(d) : "l"(a), "l"(b))
#define UNPACK2(lo, hi, v) asm("mov.b64 {%0, %1}, %2;" : "=f"(lo), "=f"(hi) : "l"(v))

// ---------------- mma / ldmatrix / cp.async helpers ----------------
__device__ __forceinline__ uint32_t smem_u32(const void* p){
    uint32_t a;
    asm("{ .reg .u64 t; cvta.to.shared.u64 t, %1; cvt.u32.u64 %0, t; }"
        : "=r"(a) : "l"(p));
    return a;
}
#define LDSM_X4(r0,r1,r2,r3,addr) asm volatile( \
    "ldmatrix.sync.aligned.m8n8.x4.shared.b16 {%0,%1,%2,%3}, [%4];" \
    : "=r"(r0), "=r"(r1), "=r"(r2), "=r"(r3) : "r"(addr))
#define LDSM_X2(r0,r1,addr) asm volatile( \
    "ldmatrix.sync.aligned.m8n8.x2.shared.b16 {%0,%1}, [%2];" \
    : "=r"(r0), "=r"(r1) : "r"(addr))
#define MMA_BF16(c0,c1,c2,c3,a0,a1,a2,a3,b0,b1) asm volatile( \
    "mma.sync.aligned.m16n8k16.row.col.f32.bf16.bf16.f32 " \
    "{%0,%1,%2,%3}, {%4,%5,%6,%7}, {%8,%9}, {%0,%1,%2,%3};" \
    : "+f"(c0), "+f"(c1), "+f"(c2), "+f"(c3) \
    : "r"(a0), "r"(a1), "r"(a2), "r"(a3), "r"(b0), "r"(b1))
#define CP16(dst, src) asm volatile( \
    "cp.async.cg.shared.global [%0], [%1], 16;" :: "r"(dst), "l"(src))
#define CP_COMMIT() asm volatile("cp.async.commit_group;" ::: "memory")
#define CP_WAIT(n)  asm volatile("cp.async.wait_group %0;" :: "n"(n) : "memory")

// ---------------- prep: fold BN, transpose, bf16 hi/lo split ----------------
__global__ void prep_kernel(
    const float* __restrict__ w1, const float* __restrict__ b1,
    const float* __restrict__ g1, const float* __restrict__ be1,
    const float* __restrict__ m1, const float* __restrict__ v1,
    const float* __restrict__ w2,
    const float* __restrict__ cw1, const float* __restrict__ cb1,
    const float* __restrict__ cg1, const float* __restrict__ cbe1,
    const float* __restrict__ cm1, const float* __restrict__ cv1,
    const float* __restrict__ cw2, const float* __restrict__ cb2,
    const float* __restrict__ cg2, const float* __restrict__ cbe2,
    const float* __restrict__ cm2, const float* __restrict__ cv2)
{
    int idx = blockIdx.x*blockDim.x + threadIdx.x;
    if (idx < 64*134){
        int co = idx/134, k = idx - co*134;
        float s = g1[co]*rsqrtf(v1[co]+1e-5f);
        g_w1t[idx] = (k < 131) ? w1[k*64+co]*s : 0.f;
        return;
    }
    idx -= 64*134;
    if (idx < 64*70){
        int co = idx/70, c = idx - co*70;
        g_w2t[idx] = (c < 64) ? w2[c*64+co] : 0.f;
        return;
    }
    idx -= 64*70;
    if (idx < 9*64*64){
        int t = idx >> 12, co = (idx >> 6) & 63, ci = idx & 63;
        float s = cg1[co]*rsqrtf(cv1[co]+1e-5f);
        float wf = cw1[(co*64+ci)*9 + t]*s;
        __nv_bfloat16 hi = __float2bfloat16(wf);
        g_cw1h[idx] = hi;
        g_cw1l[idx] = __float2bfloat16(wf - __bfloat162float(hi));
        return;
    }
    idx -= 9*64*64;
    if (idx < 9*64*64){
        int t = idx >> 12, co = (idx >> 6) & 63, ci = idx & 63;
        float s = cg2[co]*rsqrtf(cv2[co]+1e-5f);
        float wf = cw2[(co*64+ci)*9 + t]*s;
        __nv_bfloat16 hi = __float2bfloat16(wf);
        g_cw2h[idx] = hi;
        g_cw2l[idx] = __float2bfloat16(wf - __bfloat162float(hi));
        return;
    }
    idx -= 9*64*64;
    if (idx < 64){
        float s = g1[idx]*rsqrtf(v1[idx]+1e-5f);
        g_fb1[idx] = (b1[idx]-m1[idx])*s + be1[idx];
        return;
    }
    idx -= 64;
    if (idx < 64){
        float s = cg1[idx]*rsqrtf(cv1[idx]+1e-5f);
        g_cb1[idx] = (cb1[idx]-cm1[idx])*s + cbe1[idx];
        return;
    }
    idx -= 64;
    if (idx < 64){
        float s = cg2[idx]*rsqrtf(cv2[idx]+1e-5f);
        g_cb2[idx] = (cb2[idx]-cm2[idx])*s + cbe2[idx];
    }
}

// ---------------- zero BEV grid ----------------
__global__ void zero_kernel(){
    size_t i = (size_t)blockIdx.x*blockDim.x + threadIdx.x;
    size_t n4 = GRID_ELEMS/4;
    if (i < n4) ((float4*)g_bev)[i] = make_float4(0.f,0.f,0.f,0.f);
}

// ---------------- point MLP + scatter-max (R6, passing) ----------------
#define MLP_ITERS 4
#define NCHUNKS   6250
#define MLP_SMEM_FLOATS (64*134 + 64*70 + 64*132 + 64*68 + 64 + 64 + 64)

__global__ __launch_bounds__(128, 2)
void mlp_scatter_kernel(const float* __restrict__ points,
                        const float* __restrict__ features,
                        const float* __restrict__ b2)
{
    extern __shared__ float sm[];
    float* s_w1t  = sm;
    float* s_w2t  = s_w1t + 64*134;
    float* s_comb = s_w2t + 64*70;
    float* s_h    = s_comb + 64*132;
    float* s_fb1  = s_h + 64*68;
    float* s_b2   = s_fb1 + 64;
    int*   s_info = (int*)(s_b2 + 64);

    int tid = threadIdx.x;
    int cg = tid & 15;
    int pg = tid >> 4;

    for (int i = tid; i < 64*134; i += 128) s_w1t[i] = g_w1t[i];
    for (int i = tid; i < 64*70;  i += 128) s_w2t[i] = g_w2t[i];
    if (tid < 64){ s_fb1[tid] = g_fb1[tid]; s_b2[tid] = b2[tid]; }
    __syncthreads();

    const float* w1p0 = s_w1t + cg*134;
    const float* w1p1 = s_w1t + (cg+16)*134;
    const float* w1p2 = s_w1t + (cg+32)*134;
    const float* w1p3 = s_w1t + (cg+48)*134;
    const float* w2p0 = s_w2t + cg*70;
    const float* w2p1 = s_w2t + (cg+16)*70;
    const float* w2p2 = s_w2t + (cg+32)*70;
    const float* w2p3 = s_w2t + (cg+48)*70;

    for (int it = 0; it < MLP_ITERS; ++it){
        int chunk = blockIdx.x*MLP_ITERS + it;
        if (chunk >= NCHUNKS) break;
        int g0 = chunk * 64;
        {
            const float4* fsrc = (const float4*)(features + (size_t)g0*128);
            #pragma unroll
            for (int i = 0; i < 16; ++i){
                int idx = tid + i*128;
                int pt = idx >> 5, c4 = idx & 31;
                ((float4*)&s_comb[pt*132])[c4] = fsrc[pt*32 + c4];
            }
            if (tid < 64){
                int g = g0 + tid;
                float x = points[(size_t)g*3+0];
                float y = points[(size_t)g*3+1];
                float z = points[(size_t)g*3+2];
                bool valid = (x >= -50.f) && (x < 50.f) && (y >= -50.f) &&
                             (y < 50.f) && (z >= -3.f) && (z < 5.f);
                s_comb[tid*132+128] = __fdiv_rn(x + 50.f, 100.f);
                s_comb[tid*132+129] = __fdiv_rn(y + 50.f, 100.f);
                s_comb[tid*132+130] = __fdiv_rn(z + 3.f, 8.f);
                s_comb[tid*132+131] = 0.f;
                int info = -1;
                if (valid){
                    int col = (int)__fdiv_rn(x + 50.f, 0.390625f);
                    int row = (int)__fdiv_rn(y + 50.f, 0.390625f);
                    col = min(max(col,0),255); row = min(max(row,0),255);
                    int b = g / NPTS;
                    info = (b<<18) | (row<<9) | col;
                }
                s_info[tid] = info;
            }
        }
        __syncthreads();
        {
            unsigned long long acc[8][4];
            #pragma unroll
            for (int i = 0; i < 8; ++i)
                #pragma unroll
                for (int j = 0; j < 4; ++j) acc[i][j] = 0ULL;
            const float* xbase = s_comb + (pg*8)*132;
            #pragma unroll 3
            for (int k4 = 0; k4 < 33; ++k4){
                unsigned long long w0a = *(const unsigned long long*)(w1p0 + k4*4);
                unsigned long long w0b = *(const unsigned long long*)(w1p0 + k4*4 + 2);
                unsigned long long w1a = *(const unsigned long long*)(w1p1 + k4*4);
                unsigned long long w1b = *(const unsigned long long*)(w1p1 + k4*4 + 2);
                unsigned long long w2a = *(const unsigned long long*)(w1p2 + k4*4);
                unsigned long long w2b = *(const unsigned long long*)(w1p2 + k4*4 + 2);
                unsigned long long w3a = *(const unsigned long long*)(w1p3 + k4*4);
                unsigned long long w3b = *(const unsigned long long*)(w1p3 + k4*4 + 2);
                #pragma unroll
                for (int i = 0; i < 8; ++i){
                    ulonglong2 xv = *(const ulonglong2*)(xbase + i*132 + k4*4);
                    FMA2(acc[i][0], xv.x, w0a); FMA2(acc[i][0], xv.y, w0b);
                    FMA2(acc[i][1], xv.x, w1a); FMA2(acc[i][1], xv.y, w1b);
                    FMA2(acc[i][2], xv.x, w2a); FMA2(acc[i][2], xv.y, w2b);
                    FMA2(acc[i][3], xv.x, w3a); FMA2(acc[i][3], xv.y, w3b);
                }
            }
            float fb[4] = { s_fb1[cg], s_fb1[cg+16], s_fb1[cg+32], s_fb1[cg+48] };
            #pragma unroll
            for (int i = 0; i < 8; ++i)
                #pragma unroll
                for (int j = 0; j < 4; ++j){
                    float lo, hi;
                    UNPACK2(lo, hi, acc[i][j]);
                    s_h[(pg*8+i)*68 + cg + 16*j] = fmaxf(lo + hi + fb[j], 0.f);
                }
        }
        __syncthreads();
        {
            unsigned long long acc[8][4];
            #pragma unroll
            for (int i = 0; i < 8; ++i)
                #pragma unroll
                for (int j = 0; j < 4; ++j) acc[i][j] = 0ULL;
            const float* xbase = s_h + (pg*8)*68;
            #pragma unroll 4
            for (int k4 = 0; k4 < 16; ++k4){
                unsigned long long w0a = *(const unsigned long long*)(w2p0 + k4*4);
                unsigned long long w0b = *(const unsigned long long*)(w2p0 + k4*4 + 2);
                unsigned long long w1a = *(const unsigned long long*)(w2p1 + k4*4);
                unsigned long long w1b = *(const unsigned long long*)(w2p1 + k4*4 + 2);
                unsigned long long w2a = *(const unsigned long long*)(w2p2 + k4*4);
                unsigned long long w2b = *(const unsigned long long*)(w2p2 + k4*4 + 2);
                unsigned long long w3a = *(const unsigned long long*)(w2p3 + k4*4);
                unsigned long long w3b = *(const unsigned long long*)(w2p3 + k4*4 + 2);
                #pragma unroll
                for (int i = 0; i < 8; ++i){
                    ulonglong2 xv = *(const ulonglong2*)(xbase + i*68 + k4*4);
                    FMA2(acc[i][0], xv.x, w0a); FMA2(acc[i][0], xv.y, w0b);
                    FMA2(acc[i][1], xv.x, w1a); FMA2(acc[i][1], xv.y, w1b);
                    FMA2(acc[i][2], xv.x, w2a); FMA2(acc[i][2], xv.y, w2b);
                    FMA2(acc[i][3], xv.x, w3a); FMA2(acc[i][3], xv.y, w3b);
                }
            }
            float bb[4] = { s_b2[cg], s_b2[cg+16], s_b2[cg+32], s_b2[cg+48] };
            #pragma unroll
            for (int i = 0; i < 8; ++i){
                int info = s_info[pg*8+i];
                if (info < 0) continue;
                int b   = info >> 18;
                int row = (info >> 9) & 511;
                int colc = info & 511;
                size_t obase = ((size_t)(b*64 + cg)*HPAD + row + 1)*WPAD + colc + 1;
                #pragma unroll
                for (int j = 0; j < 4; ++j){
                    float lo, hi;
                    UNPACK2(lo, hi, acc[i][j]);
                    float v = lo + hi + bb[j];
                    if (v > 0.f)
                        atomicMax((unsigned int*)&g_bev[obase + (size_t)(16*j)*PLANE_PAD],
                                  __float_as_uint(v));
                }
            }
        }
        __syncthreads();
    }
}

// ---------------- bev fp32 NCHW -> NHWC bf16 hi/lo ----------------
__global__ __launch_bounds__(256)
void bev2bf16_kernel(){
    __shared__ float ts[64*65];
    int b = blockIdx.z, h = blockIdx.y, w0 = blockIdx.x*64;
    int tid = threadIdx.x;
    #pragma unroll
    for (int i = 0; i < 16; ++i){
        int idx = tid + i*256;
        int ch = idx >> 6, px = idx & 63;
        ts[ch*65 + px] = g_bev[(size_t)(b*64+ch)*PLANE_PAD
                               + (size_t)(h+1)*WPAD + (w0+1+px)];
    }
    __syncthreads();
    int px = tid >> 2, cq = (tid & 3) * 16;
    size_t base = (((size_t)b*HPAD + h + 1)*WPAD + (w0+1+px))*64 + cq;
    uint32_t hp[8], lp[8];
    #pragma unroll
    for (int j = 0; j < 8; ++j){
        float v0 = ts[(cq+2*j)*65 + px];
        float v1 = ts[(cq+2*j+1)*65 + px];
        __nv_bfloat16 h0 = __float2bfloat16(v0);
        __nv_bfloat16 h1 = __float2bfloat16(v1);
        __nv_bfloat16 l0 = __float2bfloat16(v0 - __bfloat162float(h0));
        __nv_bfloat16 l1 = __float2bfloat16(v1 - __bfloat162float(h1));
        hp[j] = (uint32_t)__bfloat16_as_ushort(h0) |
                ((uint32_t)__bfloat16_as_ushort(h1) << 16);
        lp[j] = (uint32_t)__bfloat16_as_ushort(l0) |
                ((uint32_t)__bfloat16_as_ushort(l1) << 16);
    }
    *(uint4*)(g_c1h + base)     = *(uint4*)&hp[0];
    *(uint4*)(g_c1h + base + 8) = *(uint4*)&hp[4];
    *(uint4*)(g_c1l + base)     = *(uint4*)&lp[0];
    *(uint4*)(g_c1l + base + 8) = *(uint4*)&lp[4];
}

// ---------------- tensor-core conv via mma.sync bf16 (3-term split) ----------------
// CTA: 128 px (one row segment) x 64 co. 8 warps: wm = wq&3 (M 32), wn = wq>>2 (N 32).
// smem: Abuf[2] (hi 16640 + lo 16640), Wbuf[2] (hi 8192 + lo 8192), bias 256.
#define SA_BUF   33280
#define SW_OFF   (2*SA_BUF)            // 66560
#define SW_BUF   16384
#define SBIAS    (SW_OFF + 2*SW_BUF)   // 99328
#define CONV_SMEM_BYTES (SBIAS + 256)  // 99584

template<int MODE>
__global__ __launch_bounds__(256, 2)
void conv_mma_kernel(const __nv_bfloat16* __restrict__ in_h,
                     const __nv_bfloat16* __restrict__ in_l,
                     const __nv_bfloat16* __restrict__ w_h,
                     const __nv_bfloat16* __restrict__ w_l,
                     const float* __restrict__ bias,
                     __nv_bfloat16* __restrict__ out_h,
                     __nv_bfloat16* __restrict__ out_l,
                     float* __restrict__ out_f)
{
    extern __shared__ char smem[];
    uint32_t sbase = smem_u32(smem);
    float* s_bias = (float*)(smem + SBIAS);

    int tid = threadIdx.x;
    int lane = tid & 31;
    int wq = tid >> 5;
    int wm = wq & 3;            // M warp (rows 32*wm)
    int wn = wq >> 2;           // N warp (cols 32*wn)
    int b = blockIdx.z, h = blockIdx.y, W0 = blockIdx.x * 128;

    if (tid < 64) s_bias[tid] = bias[tid];

    // lane decomposition for ldmatrix addressing
    int tile = lane >> 3;
    int r16  = ((tile & 1) << 3) + (lane & 7);   // row within m16 for A
    int kcA  = tile >> 1;                        // k-chunk half for A (x4)
    int coL  = (lane & 7);                       // row within n8 for B
    int kcB  = tile & 1;                         // k-chunk half for B (x2)

    auto stage_strip = [&](int dh, int buf){
        const char* srch = (const char*)(in_h +
            (((size_t)b*HPAD + h + dh)*WPAD + W0)*64);
        const char* srcl = (const char*)(in_l +
            (((size_t)b*HPAD + h + dh)*WPAD + W0)*64);
        uint32_t dsth = sbase + buf*SA_BUF;
        uint32_t dstl = dsth + 16640;
        #pragma unroll 1
        for (int ch = tid; ch < 1040; ch += 256){
            int px = ch >> 3, c = ch & 7;
            uint32_t off = px*128 + ((c ^ (px & 7)) << 4);
            CP16(dsth + off, srch + ch*16);
            CP16(dstl + off, srcl + ch*16);
        }
    };
    auto stage_w = [&](int t, int buf){
        const char* srch = (const char*)(w_h + t*4096);
        const char* srcl = (const char*)(w_l + t*4096);
        uint32_t dsth = sbase + SW_OFF + buf*SW_BUF;
        uint32_t dstl = dsth + 8192;
        #pragma unroll 1
        for (int ch = tid; ch < 512; ch += 256){
            int co = ch >> 3, c = ch & 7;
            uint32_t off = co*128 + ((c ^ (co & 7)) << 4);
            CP16(dsth + off, srch + ch*16);
            CP16(dstl + off, srcl + ch*16);
        }
    };

    float acc[2][4][4];
    #pragma unroll
    for (int im = 0; im < 2; ++im)
        #pragma unroll
        for (int in = 0; in < 4; ++in)
            #pragma unroll
            for (int r = 0; r < 4; ++r) acc[im][in][r] = 0.f;

    stage_strip(0, 0);
    stage_w(0, 0);
    CP_COMMIT();

    #pragma unroll 1
    for (int t = 0; t < 9; ++t){
        int dh = t / 3, dw = t - dh*3;
        if (t < 8){
            stage_w(t+1, (t+1) & 1);
            if ((t+1) % 3 == 0) stage_strip((t+1)/3, ((t+1)/3) & 1);
            CP_COMMIT();
            CP_WAIT(1);
        } else {
            CP_WAIT(0);
        }
        __syncthreads();

        uint32_t Ah = sbase + (dh & 1)*SA_BUF;
        uint32_t Al = Ah + 16640;
        uint32_t Wh = sbase + SW_OFF + (t & 1)*SW_BUF;
        uint32_t Wl = Wh + 8192;

        #pragma unroll
        for (int ks = 0; ks < 4; ++ks){
            uint32_t ah[2][4], al[2][4], bh[4][2], bl[4][2];
            #pragma unroll
            for (int im = 0; im < 2; ++im){
                int px = dw + 32*wm + 16*im + r16;
                int chunk = 2*ks + kcA;
                uint32_t ad = Ah + px*128 + ((chunk ^ (px & 7)) << 4);
                LDSM_X4(ah[im][0], ah[im][1], ah[im][2], ah[im][3], ad);
            }
            #pragma unroll
            for (int in = 0; in < 4; ++in){
                int co = 32*wn + 8*in + coL;
                int chunk = 2*ks + kcB;
                uint32_t bd = Wh + co*128 + ((chunk ^ (co & 7)) << 4);
                LDSM_X2(bh[in][0], bh[in][1], bd);
            }
            #pragma unroll
            for (int im = 0; im < 2; ++im)
                #pragma unroll
                for (int in = 0; in < 4; ++in)
                    MMA_BF16(acc[im][in][0], acc[im][in][1],
                             acc[im][in][2], acc[im][in][3],
                             ah[im][0], ah[im][1], ah[im][2], ah[im][3],
                             bh[in][0], bh[in][1]);
            #pragma unroll
            for (int in = 0; in < 4; ++in){
                int co = 32*wn + 8*in + coL;
                int chunk = 2*ks + kcB;
                uint32_t bd = Wl + co*128 + ((chunk ^ (co & 7)) << 4);
                LDSM_X2(bl[in][0], bl[in][1], bd);
            }
            #pragma unroll
            for (int im = 0; im < 2; ++im)
                #pragma unroll
                for (int in = 0; in < 4; ++in)
                    MMA_BF16(acc[im][in][0], acc[im][in][1],
                             acc[im][in][2], acc[im][in][3],
                             ah[im][0], ah[im][1], ah[im][2], ah[im][3],
                             bl[in][0], bl[in][1]);
            #pragma unroll
            for (int im = 0; im < 2; ++im){
                int px = dw + 32*wm + 16*im + r16;
                int chunk = 2*ks + kcA;
                uint32_t ad = Al + px*128 + ((chunk ^ (px & 7)) << 4);
                LDSM_X4(al[im][0], al[im][1], al[im][2], al[im][3], ad);
            }
            #pragma unroll
            for (int im = 0; im < 2; ++im)
                #pragma unroll
                for (int in = 0; in < 4; ++in)
                    MMA_BF16(acc[im][in][0], acc[im][in][1],
                             acc[im][in][2], acc[im][in][3],
                             al[im][0], al[im][1], al[im][2], al[im][3],
                             bh[in][0], bh[in][1]);
        }
        __syncthreads();
    }

    // ---- epilogue ----
    // acc[im][in][r]: row = 32wm+16im + lane/4 + 8*(r>=2); col = 32wn+8in+2*(lane&3)+(r&1)
    int rbase = 32*wm + (lane >> 2);
    int cbase = 32*wn + 2*(lane & 3);
    #pragma unroll
    for (int im = 0; im < 2; ++im){
        #pragma unroll
        for (int in = 0; in < 4; ++in){
            int c0 = cbase + 8*in;
            float bia = s_bias[c0], bib = s_bias[c0+1];
            #pragma unroll
            for (int half = 0; half < 2; ++half){
                int px = rbase + 16*im + 8*half;
                float v0 = fmaxf(acc[im][in][2*half]   + bia, 0.f);
                float v1 = fmaxf(acc[im][in][2*half+1] + bib, 0.f);
                if (MODE == 0){
                    __nv_bfloat16 h0 = __float2bfloat16(v0);
                    __nv_bfloat16 h1 = __float2bfloat16(v1);
                    __nv_bfloat16 l0 = __float2bfloat16(v0 - __bfloat162float(h0));
                    __nv_bfloat16 l1 = __float2bfloat16(v1 - __bfloat162float(h1));
                    uint32_t hp = (uint32_t)__bfloat16_as_ushort(h0) |
                                  ((uint32_t)__bfloat16_as_ushort(h1) << 16);
                    uint32_t lp = (uint32_t)__bfloat16_as_ushort(l0) |
                                  ((uint32_t)__bfloat16_as_ushort(l1) << 16);
                    size_t e = (((size_t)b*HPAD + h + 1)*WPAD + (W0 + px + 1))*64 + c0;
                    *(uint32_t*)(out_h + e) = hp;
                    *(uint32_t*)(out_l + e) = lp;
                } else {
                    size_t e = ((size_t)(b*64 + c0)*HN + h)*WN + W0 + px;
                    out_f[e] = v0;
                    out_f[e + (size_t)HN*WN] = v1;
                }
            }
        }
    }
}

// ---------------- launch ----------------
extern "C" void kernel_launch(void* const* d_in, const int* in_sizes, int n_in,
                              void* d_out, int out_size)
{
    const float* points   = (const float*)d_in[0];
    const float* features = (const float*)d_in[1];
    const float* w1   = (const float*)d_in[2];
    const float* b1   = (const float*)d_in[3];
    const float* g1   = (const float*)d_in[4];
    const float* be1  = (const float*)d_in[5];
    const float* m1   = (const float*)d_in[6];
    const float* v1   = (const float*)d_in[7];
    const float* w2   = (const float*)d_in[8];
    const float* b2   = (const float*)d_in[9];
    const float* cw1  = (const float*)d_in[10];
    const float* cb1  = (const float*)d_in[11];
    const float* cg1  = (const float*)d_in[12];
    const float* cbe1 = (const float*)d_in[13];
    const float* cm1  = (const float*)d_in[14];
    const float* cv1  = (const float*)d_in[15];
    const float* cw2  = (const float*)d_in[16];
    const float* cb2  = (const float*)d_in[17];
    const float* cg2  = (const float*)d_in[18];
    const float* cbe2 = (const float*)d_in[19];
    const float* cm2  = (const float*)d_in[20];
    const float* cv2  = (const float*)d_in[21];
    float* out = (float*)d_out;

    void *p_c1h, *p_c1l, *p_c2h, *p_c2l;
    void *p_w1h, *p_w1l, *p_w2h, *p_w2l, *p_cb1, *p_cb2;
    cudaGetSymbolAddress(&p_c1h, g_c1h);
    cudaGetSymbolAddress(&p_c1l, g_c1l);
    cudaGetSymbolAddress(&p_c2h, g_c2h);
    cudaGetSymbolAddress(&p_c2l, g_c2l);
    cudaGetSymbolAddress(&p_w1h, g_cw1h);
    cudaGetSymbolAddress(&p_w1l, g_cw1l);
    cudaGetSymbolAddress(&p_w2h, g_cw2h);
    cudaGetSymbolAddress(&p_w2l, g_cw2l);
    cudaGetSymbolAddress(&p_cb1, g_cb1);
    cudaGetSymbolAddress(&p_cb2, g_cb2);

    int mlp_smem = MLP_SMEM_FLOATS * 4;
    cudaFuncSetAttribute(mlp_scatter_kernel,
        cudaFuncAttributeMaxDynamicSharedMemorySize, mlp_smem);
    cudaFuncSetAttribute(conv_mma_kernel<0>,
        cudaFuncAttributeMaxDynamicSharedMemorySize, CONV_SMEM_BYTES);
    cudaFuncSetAttribute(conv_mma_kernel<1>,
        cudaFuncAttributeMaxDynamicSharedMemorySize, CONV_SMEM_BYTES);

    // 1) fold weights (+ bf16 hi/lo split)
    int prep_total = 64*134 + 64*70 + 2*9*64*64 + 3*64;
    prep_kernel<<<(prep_total+255)/256, 256>>>(
        w1,b1,g1,be1,m1,v1, w2,
        cw1,cb1,cg1,cbe1,cm1,cv1,
        cw2,cb2,cg2,cbe2,cm2,cv2);

    // 2) zero BEV grid
    size_t n4 = GRID_ELEMS/4;
    zero_kernel<<<(int)((n4+255)/256), 256>>>();

    // 3) point MLP + scatter-max
    int mlp_blocks = (NCHUNKS + MLP_ITERS - 1) / MLP_ITERS;
    mlp_scatter_kernel<<<mlp_blocks, 128, mlp_smem>>>(points, features, b2);

    // 4) convert bev -> NHWC bf16 hi/lo
    bev2bf16_kernel<<<dim3(4, HN, BATCH), 256>>>();

    // 5) conv1 (mma.sync): g_c1 -> g_c2 (NHWC bf16 hi/lo, padded)
    dim3 cgrid(2, HN, BATCH);
    conv_mma_kernel<0><<<cgrid, 256, CONV_SMEM_BYTES>>>(
        (const __nv_bfloat16*)p_c1h, (const __nv_bfloat16*)p_c1l,
        (const __nv_bfloat16*)p_w1h, (const __nv_bfloat16*)p_w1l,
        (const float*)p_cb1,
        (__nv_bfloat16*)p_c2h, (__nv_bfloat16*)p_c2l, nullptr);

    // 6) conv2 (mma.sync): g_c2 -> d_out (NCHW fp32)
    conv_mma_kernel<1><<<cgrid, 256, CONV_SMEM_BYTES>>>(
        (const __nv_bfloat16*)p_c2h, (const __nv_bfloat16*)p_c2l,
        (const __nv_bfloat16*)p_w2h, (const __nv_bfloat16*)p_w2l,
        (const float*)p_cb2,
        nullptr, nullptr, out);
}

// round 8
// speedup vs baseline: 2.5262x; 1.3331x over previous
#include <cuda_runtime.h>
#include <cuda_bf16.h>
#include <cstdint>

// ---------------- constants ----------------
#define HN     256
#define WN     256
#define HPAD   258
#define WPAD   258
#define NPTS   100000
#define BATCH  4
#define TOTPTS 400000
#define PLANE_PAD (HPAD*WPAD)                        // 66564
#define GRID_ELEMS ((size_t)BATCH*64*HPAD*WPAD)      // 17,040,384

// ---------------- device scratch ----------------
__device__ float g_bev[GRID_ELEMS];                  // fp32 NCHW padded (scatter target)
__device__ __nv_bfloat16 g_c1h[GRID_ELEMS];          // conv1 input NHWC padded, hi
__device__ __nv_bfloat16 g_c1l[GRID_ELEMS];          // lo
__device__ __nv_bfloat16 g_c2h[GRID_ELEMS];          // conv2 input NHWC padded, hi
__device__ __nv_bfloat16 g_c2l[GRID_ELEMS];          // lo
__device__ __nv_bfloat16 g_cw1h[9*64*64];            // [tap][co][ci] bf16 hi, BN-folded
__device__ __nv_bfloat16 g_cw1l[9*64*64];
__device__ __nv_bfloat16 g_cw2h[9*64*64];
__device__ __nv_bfloat16 g_cw2l[9*64*64];
__device__ __nv_bfloat16 g_mw1h[2*64*64];            // MLP L1 W [panel][co][k] hi (k<128)
__device__ __nv_bfloat16 g_mw1l[2*64*64];
__device__ __nv_bfloat16 g_mw2h[64*64];              // MLP L2 W [co][c]
__device__ __nv_bfloat16 g_mw2l[64*64];
__device__ float g_w1p[3*64];                        // pos rows of W1 (BN-folded, fp32)
__device__ float g_fb1[64];
__device__ float g_cb1[64];
__device__ float g_cb2[64];

// ---------------- mma / ldmatrix / cp.async helpers ----------------
__device__ __forceinline__ uint32_t smem_u32(const void* p){
    uint32_t a;
    asm("{ .reg .u64 t; cvta.to.shared.u64 t, %1; cvt.u32.u64 %0, t; }"
        : "=r"(a) : "l"(p));
    return a;
}
#define LDSM_X4(r0,r1,r2,r3,addr) asm volatile( \
    "ldmatrix.sync.aligned.m8n8.x4.shared.b16 {%0,%1,%2,%3}, [%4];" \
    : "=r"(r0), "=r"(r1), "=r"(r2), "=r"(r3) : "r"(addr))
#define LDSM_X2(r0,r1,addr) asm volatile( \
    "ldmatrix.sync.aligned.m8n8.x2.shared.b16 {%0,%1}, [%2];" \
    : "=r"(r0), "=r"(r1) : "r"(addr))
#define MMA_BF16(c0,c1,c2,c3,a0,a1,a2,a3,b0,b1) asm volatile( \
    "mma.sync.aligned.m16n8k16.row.col.f32.bf16.bf16.f32 " \
    "{%0,%1,%2,%3}, {%4,%5,%6,%7}, {%8,%9}, {%0,%1,%2,%3};" \
    : "+f"(c0), "+f"(c1), "+f"(c2), "+f"(c3) \
    : "r"(a0), "r"(a1), "r"(a2), "r"(a3), "r"(b0), "r"(b1))
#define CP16(dst, src) asm volatile( \
    "cp.async.cg.shared.global [%0], [%1], 16;" :: "r"(dst), "l"(src))
#define CP_COMMIT() asm volatile("cp.async.commit_group;" ::: "memory")
#define CP_WAIT(n)  asm volatile("cp.async.wait_group %0;" :: "n"(n) : "memory")

// ---------------- prep: fold BN, emit bf16 hi/lo weights ----------------
__global__ void prep_kernel(
    const float* __restrict__ w1, const float* __restrict__ b1,
    const float* __restrict__ g1, const float* __restrict__ be1,
    const float* __restrict__ m1, const float* __restrict__ v1,
    const float* __restrict__ w2,
    const float* __restrict__ cw1, const float* __restrict__ cb1,
    const float* __restrict__ cg1, const float* __restrict__ cbe1,
    const float* __restrict__ cm1, const float* __restrict__ cv1,
    const float* __restrict__ cw2, const float* __restrict__ cb2,
    const float* __restrict__ cg2, const float* __restrict__ cbe2,
    const float* __restrict__ cm2, const float* __restrict__ cv2)
{
    int idx = blockIdx.x*blockDim.x + threadIdx.x;
    if (idx < 8192){                      // MLP W1 k<128: [panel][co][kk]
        int p = idx >> 12, r = idx & 4095, co = r >> 6, kk = r & 63;
        int k = p*64 + kk;
        float s = g1[co]*rsqrtf(v1[co]+1e-5f);
        float wf = w1[k*64+co]*s;
        __nv_bfloat16 hi = __float2bfloat16(wf);
        g_mw1h[idx] = hi;
        g_mw1l[idx] = __float2bfloat16(wf - __bfloat162float(hi));
        return;
    }
    idx -= 8192;
    if (idx < 4096){                      // MLP W2: [co][c]
        int co = idx >> 6, c = idx & 63;
        float wf = w2[c*64+co];
        __nv_bfloat16 hi = __float2bfloat16(wf);
        g_mw2h[idx] = hi;
        g_mw2l[idx] = __float2bfloat16(wf - __bfloat162float(hi));
        return;
    }
    idx -= 4096;
    if (idx < 192){                       // pos rows of W1, fp32
        int i = idx >> 6, co = idx & 63;
        float s = g1[co]*rsqrtf(v1[co]+1e-5f);
        g_w1p[idx] = w1[(128+i)*64+co]*s;
        return;
    }
    idx -= 192;
    if (idx < 64){
        float s = g1[idx]*rsqrtf(v1[idx]+1e-5f);
        g_fb1[idx] = (b1[idx]-m1[idx])*s + be1[idx];
        return;
    }
    idx -= 64;
    if (idx < 9*64*64){
        int t = idx >> 12, co = (idx >> 6) & 63, ci = idx & 63;
        float s = cg1[co]*rsqrtf(cv1[co]+1e-5f);
        float wf = cw1[(co*64+ci)*9 + t]*s;
        __nv_bfloat16 hi = __float2bfloat16(wf);
        g_cw1h[idx] = hi;
        g_cw1l[idx] = __float2bfloat16(wf - __bfloat162float(hi));
        return;
    }
    idx -= 9*64*64;
    if (idx < 9*64*64){
        int t = idx >> 12, co = (idx >> 6) & 63, ci = idx & 63;
        float s = cg2[co]*rsqrtf(cv2[co]+1e-5f);
        float wf = cw2[(co*64+ci)*9 + t]*s;
        __nv_bfloat16 hi = __float2bfloat16(wf);
        g_cw2h[idx] = hi;
        g_cw2l[idx] = __float2bfloat16(wf - __bfloat162float(hi));
        return;
    }
    idx -= 9*64*64;
    if (idx < 64){
        float s = cg1[idx]*rsqrtf(cv1[idx]+1e-5f);
        g_cb1[idx] = (cb1[idx]-cm1[idx])*s + cbe1[idx];
        return;
    }
    idx -= 64;
    if (idx < 64){
        float s = cg2[idx]*rsqrtf(cv2[idx]+1e-5f);
        g_cb2[idx] = (cb2[idx]-cm2[idx])*s + cbe2[idx];
    }
}

// ---------------- zero BEV grid ----------------
__global__ void zero_kernel(){
    size_t i = (size_t)blockIdx.x*blockDim.x + threadIdx.x;
    size_t n4 = GRID_ELEMS/4;
    if (i < n4) ((float4*)g_bev)[i] = make_float4(0.f,0.f,0.f,0.f);
}

// ---------------- tensor-core MLP + scatter-max ----------------
// Persistent: grid 296 CTAs x 256 thr, 2/SM. Chunk = 64 points.
// smem: W1 4 panels (h0,h1,l0,l1) 32K | W2 (h,l) 16K | A 4 panels 32K |
//       Hh/Hl 16K | w1p 768 | fb1 256 | b2 256 | pos 1K | info 256
#define MLPS_W1   0
#define MLPS_W2   32768
#define MLPS_A    49152
#define MLPS_HH   81920
#define MLPS_HL   90112
#define MLPS_W1P  98304
#define MLPS_FB1  99072
#define MLPS_B2   99328
#define MLPS_POS  99584
#define MLPS_INFO 100608
#define MLP_SMEM_BYTES 100864
#define NCHUNKS 6250

__global__ __launch_bounds__(256, 2)
void mlp_mma_kernel(const float* __restrict__ points,
                    const float* __restrict__ features,
                    const float* __restrict__ b2)
{
    extern __shared__ char smem[];
    uint32_t sb = smem_u32(smem);
    float* s_w1p = (float*)(smem + MLPS_W1P);
    float* s_fb1 = (float*)(smem + MLPS_FB1);
    float* s_b2  = (float*)(smem + MLPS_B2);
    float* s_pos = (float*)(smem + MLPS_POS);    // [64][4]
    int*   s_info= (int*)(smem + MLPS_INFO);

    int tid = threadIdx.x;
    int lane = tid & 31;
    int wq = tid >> 5;
    int wm = wq & 3;            // point-rows 16*wm
    int wn = wq >> 2;           // cols 32*wn
    int tile = lane >> 3;
    int r16  = ((tile & 1) << 3) + (lane & 7);
    int kcA  = tile >> 1;
    int coL  = lane & 7;
    int kcB  = tile & 1;

    // ---- stage weights once ----
    for (int j = tid; j < 2048; j += 256){       // W1: 4 panels x 64 rows x 8 chunks
        int panel = j >> 9, r = (j >> 3) & 63, c = j & 7;
        const __nv_bfloat16* src = (panel < 2)
            ? (g_mw1h + panel*4096 + r*64 + c*8)
            : (g_mw1l + (panel-2)*4096 + r*64 + c*8);
        CP16(sb + MLPS_W1 + panel*8192 + r*128 + ((c ^ (r & 7)) << 4), src);
    }
    for (int j = tid; j < 1024; j += 256){       // W2: 2 panels
        int panel = j >> 9, r = (j >> 3) & 63, c = j & 7;
        const __nv_bfloat16* src = (panel ? g_mw2l : g_mw2h) + r*64 + c*8;
        CP16(sb + MLPS_W2 + panel*8192 + r*128 + ((c ^ (r & 7)) << 4), src);
    }
    CP_COMMIT();
    if (tid < 192) s_w1p[tid] = g_w1p[tid];
    if (tid < 64){ s_fb1[tid] = g_fb1[tid]; s_b2[tid] = b2[tid]; }
    CP_WAIT(0);
    __syncthreads();

    for (int chunk = blockIdx.x; chunk < NCHUNKS; chunk += gridDim.x){
        int g0 = chunk * 64;

        // ---- stage A: fp32 features -> bf16 hi/lo (truncation split) ----
        #pragma unroll
        for (int i = 0; i < 4; ++i){
            int j = tid + i*256;                 // 1024 jobs: 64 pts x 16 octets
            int pt = j >> 4, oct = j & 15;
            const uint4* src = (const uint4*)(features + (size_t)(g0+pt)*128 + oct*8);
            uint4 u0 = src[0], u1 = src[1];
            uint4 hv, lv;
            hv.x = __byte_perm(u0.x, u0.y, 0x7632);
            hv.y = __byte_perm(u0.z, u0.w, 0x7632);
            hv.z = __byte_perm(u1.x, u1.y, 0x7632);
            hv.w = __byte_perm(u1.z, u1.w, 0x7632);
            float l0 = __uint_as_float(u0.x) - __uint_as_float(u0.x & 0xFFFF0000u);
            float l1 = __uint_as_float(u0.y) - __uint_as_float(u0.y & 0xFFFF0000u);
            float l2 = __uint_as_float(u0.z) - __uint_as_float(u0.z & 0xFFFF0000u);
            float l3 = __uint_as_float(u0.w) - __uint_as_float(u0.w & 0xFFFF0000u);
            float l4 = __uint_as_float(u1.x) - __uint_as_float(u1.x & 0xFFFF0000u);
            float l5 = __uint_as_float(u1.y) - __uint_as_float(u1.y & 0xFFFF0000u);
            float l6 = __uint_as_float(u1.z) - __uint_as_float(u1.z & 0xFFFF0000u);
            float l7 = __uint_as_float(u1.w) - __uint_as_float(u1.w & 0xFFFF0000u);
            lv.x = __byte_perm(__float_as_uint(l0), __float_as_uint(l1), 0x7632);
            lv.y = __byte_perm(__float_as_uint(l2), __float_as_uint(l3), 0x7632);
            lv.z = __byte_perm(__float_as_uint(l4), __float_as_uint(l5), 0x7632);
            lv.w = __byte_perm(__float_as_uint(l6), __float_as_uint(l7), 0x7632);
            int panel = oct >> 3, c = oct & 7;
            uint32_t off = MLPS_A + panel*8192 + pt*128 + ((c ^ (pt & 7)) << 4);
            *(uint4*)(smem + off) = hv;
            *(uint4*)(smem + off + 16384) = lv;   // lo panels at +2*8192
        }
        if (tid < 64){
            int g = g0 + tid;
            float x = points[(size_t)g*3+0];
            float y = points[(size_t)g*3+1];
            float z = points[(size_t)g*3+2];
            bool valid = (x >= -50.f) && (x < 50.f) && (y >= -50.f) &&
                         (y < 50.f) && (z >= -3.f) && (z < 5.f);
            s_pos[tid*4+0] = __fdiv_rn(x + 50.f, 100.f);
            s_pos[tid*4+1] = __fdiv_rn(y + 50.f, 100.f);
            s_pos[tid*4+2] = __fdiv_rn(z + 3.f, 8.f);
            int info = -1;
            if (valid){
                int col = (int)__fdiv_rn(x + 50.f, 0.390625f);
                int row = (int)__fdiv_rn(y + 50.f, 0.390625f);
                col = min(max(col,0),255); row = min(max(row,0),255);
                int b = g / NPTS;
                info = (b<<18) | (row<<9) | col;
            }
            s_info[tid] = info;
        }
        __syncthreads();

        // ---- layer 1 GEMM: [64 pts x 128] x [64 co x 128]^T ----
        float acc[4][4];
        #pragma unroll
        for (int in = 0; in < 4; ++in)
            #pragma unroll
            for (int r = 0; r < 4; ++r) acc[in][r] = 0.f;

        int arow = 16*wm + r16;
        #pragma unroll
        for (int ks = 0; ks < 8; ++ks){
            int panel = ks >> 2, cc = 2*(ks & 3);
            uint32_t ah[4], al[4], bh[4][2], bl[4][2];
            uint32_t aad = sb + MLPS_A + panel*8192 + arow*128
                         + (((cc + kcA) ^ (arow & 7)) << 4);
            LDSM_X4(ah[0], ah[1], ah[2], ah[3], aad);
            LDSM_X4(al[0], al[1], al[2], al[3], aad + 16384);
            #pragma unroll
            for (int in = 0; in < 4; ++in){
                int co = 32*wn + 8*in + coL;
                uint32_t bad = sb + MLPS_W1 + panel*8192 + co*128
                             + (((cc + kcB) ^ (co & 7)) << 4);
                LDSM_X2(bh[in][0], bh[in][1], bad);
                LDSM_X2(bl[in][0], bl[in][1], bad + 16384);
            }
            #pragma unroll
            for (int in = 0; in < 4; ++in){
                MMA_BF16(acc[in][0],acc[in][1],acc[in][2],acc[in][3],
                         ah[0],ah[1],ah[2],ah[3], bh[in][0],bh[in][1]);
                MMA_BF16(acc[in][0],acc[in][1],acc[in][2],acc[in][3],
                         ah[0],ah[1],ah[2],ah[3], bl[in][0],bl[in][1]);
                MMA_BF16(acc[in][0],acc[in][1],acc[in][2],acc[in][3],
                         al[0],al[1],al[2],al[3], bh[in][0],bh[in][1]);
            }
        }

        // ---- epilogue 1: + pos terms (fp32) + bias, ReLU, rn-split -> H ----
        int rb = 16*wm + (lane >> 2);
        int cb = 2*(lane & 3);
        #pragma unroll
        for (int in = 0; in < 4; ++in){
            int c0 = 32*wn + 8*in + cb;
            float p0a = s_w1p[c0],      p0b = s_w1p[c0+1];
            float p1a = s_w1p[64+c0],   p1b = s_w1p[64+c0+1];
            float p2a = s_w1p[128+c0],  p2b = s_w1p[128+c0+1];
            float fba = s_fb1[c0], fbb = s_fb1[c0+1];
            int ch = c0 >> 3;
            #pragma unroll
            for (int half = 0; half < 2; ++half){
                int pt = rb + 8*half;
                float px = s_pos[pt*4], py = s_pos[pt*4+1], pz = s_pos[pt*4+2];
                float v0 = acc[in][2*half]   + fba + px*p0a + py*p1a + pz*p2a;
                float v1 = acc[in][2*half+1] + fbb + px*p0b + py*p1b + pz*p2b;
                v0 = fmaxf(v0, 0.f); v1 = fmaxf(v1, 0.f);
                __nv_bfloat16 h0 = __float2bfloat16(v0);
                __nv_bfloat16 h1 = __float2bfloat16(v1);
                __nv_bfloat16 q0 = __float2bfloat16(v0 - __bfloat162float(h0));
                __nv_bfloat16 q1 = __float2bfloat16(v1 - __bfloat162float(h1));
                uint32_t hp = (uint32_t)__bfloat16_as_ushort(h0) |
                              ((uint32_t)__bfloat16_as_ushort(h1) << 16);
                uint32_t lp = (uint32_t)__bfloat16_as_ushort(q0) |
                              ((uint32_t)__bfloat16_as_ushort(q1) << 16);
                uint32_t off = pt*128 + ((ch ^ (pt & 7)) << 4) + cb*2;
                *(uint32_t*)(smem + MLPS_HH + off) = hp;
                *(uint32_t*)(smem + MLPS_HL + off) = lp;
            }
        }
        __syncthreads();

        // ---- layer 2 GEMM: [64 pts x 64] x [64 co x 64]^T ----
        float acc2[4][4];
        #pragma unroll
        for (int in = 0; in < 4; ++in)
            #pragma unroll
            for (int r = 0; r < 4; ++r) acc2[in][r] = 0.f;

        #pragma unroll
        for (int ks = 0; ks < 4; ++ks){
            int cc = 2*ks;
            uint32_t ah[4], al[4], bh[4][2], bl[4][2];
            uint32_t aad = sb + MLPS_HH + arow*128
                         + (((cc + kcA) ^ (arow & 7)) << 4);
            LDSM_X4(ah[0], ah[1], ah[2], ah[3], aad);
            LDSM_X4(al[0], al[1], al[2], al[3], aad + 8192);
            #pragma unroll
            for (int in = 0; in < 4; ++in){
                int co = 32*wn + 8*in + coL;
                uint32_t bad = sb + MLPS_W2 + co*128
                             + (((cc + kcB) ^ (co & 7)) << 4);
                LDSM_X2(bh[in][0], bh[in][1], bad);
                LDSM_X2(bl[in][0], bl[in][1], bad + 8192);
            }
            #pragma unroll
            for (int in = 0; in < 4; ++in){
                MMA_BF16(acc2[in][0],acc2[in][1],acc2[in][2],acc2[in][3],
                         ah[0],ah[1],ah[2],ah[3], bh[in][0],bh[in][1]);
                MMA_BF16(acc2[in][0],acc2[in][1],acc2[in][2],acc2[in][3],
                         ah[0],ah[1],ah[2],ah[3], bl[in][0],bl[in][1]);
                MMA_BF16(acc2[in][0],acc2[in][1],acc2[in][2],acc2[in][3],
                         al[0],al[1],al[2],al[3], bh[in][0],bh[in][1]);
            }
        }

        // ---- epilogue 2: + b2, scatter-max ----
        #pragma unroll
        for (int in = 0; in < 4; ++in){
            int c0 = 32*wn + 8*in + cb;
            float bb0 = s_b2[c0], bb1 = s_b2[c0+1];
            #pragma unroll
            for (int half = 0; half < 2; ++half){
                int pt = rb + 8*half;
                int info = s_info[pt];
                if (info < 0) continue;
                int b   = info >> 18;
                int row = (info >> 9) & 511;
                int col = info & 511;
                float v0 = acc2[in][2*half]   + bb0;
                float v1 = acc2[in][2*half+1] + bb1;
                size_t obase = ((size_t)(b*64 + c0)*HPAD + row + 1)*WPAD + col + 1;
                if (v0 > 0.f)
                    atomicMax((unsigned int*)&g_bev[obase], __float_as_uint(v0));
                if (v1 > 0.f)
                    atomicMax((unsigned int*)&g_bev[obase + PLANE_PAD],
                              __float_as_uint(v1));
            }
        }
        __syncthreads();
    }
}

// ---------------- bev fp32 NCHW -> NHWC bf16 hi/lo ----------------
__global__ __launch_bounds__(256)
void bev2bf16_kernel(){
    __shared__ float ts[64*65];
    int b = blockIdx.z, h = blockIdx.y, w0 = blockIdx.x*64;
    int tid = threadIdx.x;
    #pragma unroll
    for (int i = 0; i < 16; ++i){
        int idx = tid + i*256;
        int ch = idx >> 6, px = idx & 63;
        ts[ch*65 + px] = g_bev[(size_t)(b*64+ch)*PLANE_PAD
                               + (size_t)(h+1)*WPAD + (w0+1+px)];
    }
    __syncthreads();
    int px = tid >> 2, cq = (tid & 3) * 16;
    size_t base = (((size_t)b*HPAD + h + 1)*WPAD + (w0+1+px))*64 + cq;
    uint32_t hp[8], lp[8];
    #pragma unroll
    for (int j = 0; j < 8; ++j){
        float v0 = ts[(cq+2*j)*65 + px];
        float v1 = ts[(cq+2*j+1)*65 + px];
        __nv_bfloat16 h0 = __float2bfloat16(v0);
        __nv_bfloat16 h1 = __float2bfloat16(v1);
        __nv_bfloat16 l0 = __float2bfloat16(v0 - __bfloat162float(h0));
        __nv_bfloat16 l1 = __float2bfloat16(v1 - __bfloat162float(h1));
        hp[j] = (uint32_t)__bfloat16_as_ushort(h0) |
                ((uint32_t)__bfloat16_as_ushort(h1) << 16);
        lp[j] = (uint32_t)__bfloat16_as_ushort(l0) |
                ((uint32_t)__bfloat16_as_ushort(l1) << 16);
    }
    *(uint4*)(g_c1h + base)     = *(uint4*)&hp[0];
    *(uint4*)(g_c1h + base + 8) = *(uint4*)&hp[4];
    *(uint4*)(g_c1l + base)     = *(uint4*)&lp[0];
    *(uint4*)(g_c1l + base + 8) = *(uint4*)&lp[4];
}

// ---------------- tensor-core conv via mma.sync bf16 (R7, unchanged) ----------------
#define SA_BUF   33280
#define SW_OFF   (2*SA_BUF)            // 66560
#define SW_BUF   16384
#define SBIAS    (SW_OFF + 2*SW_BUF)   // 99328
#define CONV_SMEM_BYTES (SBIAS + 256)  // 99584

template<int MODE>
__global__ __launch_bounds__(256, 2)
void conv_mma_kernel(const __nv_bfloat16* __restrict__ in_h,
                     const __nv_bfloat16* __restrict__ in_l,
                     const __nv_bfloat16* __restrict__ w_h,
                     const __nv_bfloat16* __restrict__ w_l,
                     const float* __restrict__ bias,
                     __nv_bfloat16* __restrict__ out_h,
                     __nv_bfloat16* __restrict__ out_l,
                     float* __restrict__ out_f)
{
    extern __shared__ char smem[];
    uint32_t sbase = smem_u32(smem);
    float* s_bias = (float*)(smem + SBIAS);

    int tid = threadIdx.x;
    int lane = tid & 31;
    int wq = tid >> 5;
    int wm = wq & 3;
    int wn = wq >> 2;
    int b = blockIdx.z, h = blockIdx.y, W0 = blockIdx.x * 128;

    if (tid < 64) s_bias[tid] = bias[tid];

    int tile = lane >> 3;
    int r16  = ((tile & 1) << 3) + (lane & 7);
    int kcA  = tile >> 1;
    int coL  = (lane & 7);
    int kcB  = tile & 1;

    auto stage_strip = [&](int dh, int buf){
        const char* srch = (const char*)(in_h +
            (((size_t)b*HPAD + h + dh)*WPAD + W0)*64);
        const char* srcl = (const char*)(in_l +
            (((size_t)b*HPAD + h + dh)*WPAD + W0)*64);
        uint32_t dsth = sbase + buf*SA_BUF;
        uint32_t dstl = dsth + 16640;
        #pragma unroll 1
        for (int ch = tid; ch < 1040; ch += 256){
            int px = ch >> 3, c = ch & 7;
            uint32_t off = px*128 + ((c ^ (px & 7)) << 4);
            CP16(dsth + off, srch + ch*16);
            CP16(dstl + off, srcl + ch*16);
        }
    };
    auto stage_w = [&](int t, int buf){
        const char* srch = (const char*)(w_h + t*4096);
        const char* srcl = (const char*)(w_l + t*4096);
        uint32_t dsth = sbase + SW_OFF + buf*SW_BUF;
        uint32_t dstl = dsth + 8192;
        #pragma unroll 1
        for (int ch = tid; ch < 512; ch += 256){
            int co = ch >> 3, c = ch & 7;
            uint32_t off = co*128 + ((c ^ (co & 7)) << 4);
            CP16(dsth + off, srch + ch*16);
            CP16(dstl + off, srcl + ch*16);
        }
    };

    float acc[2][4][4];
    #pragma unroll
    for (int im = 0; im < 2; ++im)
        #pragma unroll
        for (int in = 0; in < 4; ++in)
            #pragma unroll
            for (int r = 0; r < 4; ++r) acc[im][in][r] = 0.f;

    stage_strip(0, 0);
    stage_w(0, 0);
    CP_COMMIT();

    #pragma unroll 1
    for (int t = 0; t < 9; ++t){
        int dh = t / 3, dw = t - dh*3;
        if (t < 8){
            stage_w(t+1, (t+1) & 1);
            if ((t+1) % 3 == 0) stage_strip((t+1)/3, ((t+1)/3) & 1);
            CP_COMMIT();
            CP_WAIT(1);
        } else {
            CP_WAIT(0);
        }
        __syncthreads();

        uint32_t Ah = sbase + (dh & 1)*SA_BUF;
        uint32_t Al = Ah + 16640;
        uint32_t Wh = sbase + SW_OFF + (t & 1)*SW_BUF;
        uint32_t Wl = Wh + 8192;

        #pragma unroll
        for (int ks = 0; ks < 4; ++ks){
            uint32_t ah[2][4], al[2][4], bh[4][2], bl[4][2];
            #pragma unroll
            for (int im = 0; im < 2; ++im){
                int px = dw + 32*wm + 16*im + r16;
                int chunk = 2*ks + kcA;
                uint32_t ad = Ah + px*128 + ((chunk ^ (px & 7)) << 4);
                LDSM_X4(ah[im][0], ah[im][1], ah[im][2], ah[im][3], ad);
            }
            #pragma unroll
            for (int in = 0; in < 4; ++in){
                int co = 32*wn + 8*in + coL;
                int chunk = 2*ks + kcB;
                uint32_t bd = Wh + co*128 + ((chunk ^ (co & 7)) << 4);
                LDSM_X2(bh[in][0], bh[in][1], bd);
            }
            #pragma unroll
            for (int im = 0; im < 2; ++im)
                #pragma unroll
                for (int in = 0; in < 4; ++in)
                    MMA_BF16(acc[im][in][0], acc[im][in][1],
                             acc[im][in][2], acc[im][in][3],
                             ah[im][0], ah[im][1], ah[im][2], ah[im][3],
                             bh[in][0], bh[in][1]);
            #pragma unroll
            for (int in = 0; in < 4; ++in){
                int co = 32*wn + 8*in + coL;
                int chunk = 2*ks + kcB;
                uint32_t bd = Wl + co*128 + ((chunk ^ (co & 7)) << 4);
                LDSM_X2(bl[in][0], bl[in][1], bd);
            }
            #pragma unroll
            for (int im = 0; im < 2; ++im)
                #pragma unroll
                for (int in = 0; in < 4; ++in)
                    MMA_BF16(acc[im][in][0], acc[im][in][1],
                             acc[im][in][2], acc[im][in][3],
                             ah[im][0], ah[im][1], ah[im][2], ah[im][3],
                             bl[in][0], bl[in][1]);
            #pragma unroll
            for (int im = 0; im < 2; ++im){
                int px = dw + 32*wm + 16*im + r16;
                int chunk = 2*ks + kcA;
                uint32_t ad = Al + px*128 + ((chunk ^ (px & 7)) << 4);
                LDSM_X4(al[im][0], al[im][1], al[im][2], al[im][3], ad);
            }
            #pragma unroll
            for (int im = 0; im < 2; ++im)
                #pragma unroll
                for (int in = 0; in < 4; ++in)
                    MMA_BF16(acc[im][in][0], acc[im][in][1],
                             acc[im][in][2], acc[im][in][3],
                             al[im][0], al[im][1], al[im][2], al[im][3],
                             bh[in][0], bh[in][1]);
        }
        __syncthreads();
    }

    int rbase = 32*wm + (lane >> 2);
    int cbase = 32*wn + 2*(lane & 3);
    #pragma unroll
    for (int im = 0; im < 2; ++im){
        #pragma unroll
        for (int in = 0; in < 4; ++in){
            int c0 = cbase + 8*in;
            float bia = s_bias[c0], bib = s_bias[c0+1];
            #pragma unroll
            for (int half = 0; half < 2; ++half){
                int px = rbase + 16*im + 8*half;
                float v0 = fmaxf(acc[im][in][2*half]   + bia, 0.f);
                float v1 = fmaxf(acc[im][in][2*half+1] + bib, 0.f);
                if (MODE == 0){
                    __nv_bfloat16 h0 = __float2bfloat16(v0);
                    __nv_bfloat16 h1 = __float2bfloat16(v1);
                    __nv_bfloat16 l0 = __float2bfloat16(v0 - __bfloat162float(h0));
                    __nv_bfloat16 l1 = __float2bfloat16(v1 - __bfloat162float(h1));
                    uint32_t hp = (uint32_t)__bfloat16_as_ushort(h0) |
                                  ((uint32_t)__bfloat16_as_ushort(h1) << 16);
                    uint32_t lp = (uint32_t)__bfloat16_as_ushort(l0) |
                                  ((uint32_t)__bfloat16_as_ushort(l1) << 16);
                    size_t e = (((size_t)b*HPAD + h + 1)*WPAD + (W0 + px + 1))*64 + c0;
                    *(uint32_t*)(out_h + e) = hp;
                    *(uint32_t*)(out_l + e) = lp;
                } else {
                    size_t e = ((size_t)(b*64 + c0)*HN + h)*WN + W0 + px;
                    out_f[e] = v0;
                    out_f[e + (size_t)HN*WN] = v1;
                }
            }
        }
    }
}

// ---------------- launch ----------------
extern "C" void kernel_launch(void* const* d_in, const int* in_sizes, int n_in,
                              void* d_out, int out_size)
{
    const float* points   = (const float*)d_in[0];
    const float* features = (const float*)d_in[1];
    const float* w1   = (const float*)d_in[2];
    const float* b1   = (const float*)d_in[3];
    const float* g1   = (const float*)d_in[4];
    const float* be1  = (const float*)d_in[5];
    const float* m1   = (const float*)d_in[6];
    const float* v1   = (const float*)d_in[7];
    const float* w2   = (const float*)d_in[8];
    const float* b2   = (const float*)d_in[9];
    const float* cw1  = (const float*)d_in[10];
    const float* cb1  = (const float*)d_in[11];
    const float* cg1  = (const float*)d_in[12];
    const float* cbe1 = (const float*)d_in[13];
    const float* cm1  = (const float*)d_in[14];
    const float* cv1  = (const float*)d_in[15];
    const float* cw2  = (const float*)d_in[16];
    const float* cb2  = (const float*)d_in[17];
    const float* cg2  = (const float*)d_in[18];
    const float* cbe2 = (const float*)d_in[19];
    const float* cm2  = (const float*)d_in[20];
    const float* cv2  = (const float*)d_in[21];
    float* out = (float*)d_out;

    void *p_c1h, *p_c1l, *p_c2h, *p_c2l;
    void *p_w1h, *p_w1l, *p_w2h, *p_w2l, *p_cb1, *p_cb2;
    cudaGetSymbolAddress(&p_c1h, g_c1h);
    cudaGetSymbolAddress(&p_c1l, g_c1l);
    cudaGetSymbolAddress(&p_c2h, g_c2h);
    cudaGetSymbolAddress(&p_c2l, g_c2l);
    cudaGetSymbolAddress(&p_w1h, g_cw1h);
    cudaGetSymbolAddress(&p_w1l, g_cw1l);
    cudaGetSymbolAddress(&p_w2h, g_cw2h);
    cudaGetSymbolAddress(&p_w2l, g_cw2l);
    cudaGetSymbolAddress(&p_cb1, g_cb1);
    cudaGetSymbolAddress(&p_cb2, g_cb2);

    cudaFuncSetAttribute(mlp_mma_kernel,
        cudaFuncAttributeMaxDynamicSharedMemorySize, MLP_SMEM_BYTES);
    cudaFuncSetAttribute(conv_mma_kernel<0>,
        cudaFuncAttributeMaxDynamicSharedMemorySize, CONV_SMEM_BYTES);
    cudaFuncSetAttribute(conv_mma_kernel<1>,
        cudaFuncAttributeMaxDynamicSharedMemorySize, CONV_SMEM_BYTES);

    // 1) fold weights (+ bf16 hi/lo split)
    int prep_total = 8192 + 4096 + 192 + 64 + 2*9*64*64 + 2*64;
    prep_kernel<<<(prep_total+255)/256, 256>>>(
        w1,b1,g1,be1,m1,v1, w2,
        cw1,cb1,cg1,cbe1,cm1,cv1,
        cw2,cb2,cg2,cbe2,cm2,cv2);

    // 2) zero BEV grid
    size_t n4 = GRID_ELEMS/4;
    zero_kernel<<<(int)((n4+255)/256), 256>>>();

    // 3) tensor-core point MLP + scatter-max (persistent)
    mlp_mma_kernel<<<296, 256, MLP_SMEM_BYTES>>>(points, features, b2);

    // 4) convert bev -> NHWC bf16 hi/lo
    bev2bf16_kernel<<<dim3(4, HN, BATCH), 256>>>();

    // 5) conv1 (mma.sync): g_c1 -> g_c2 (NHWC bf16 hi/lo, padded)
    dim3 cgrid(2, HN, BATCH);
    conv_mma_kernel<0><<<cgrid, 256, CONV_SMEM_BYTES>>>(
        (const __nv_bfloat16*)p_c1h, (const __nv_bfloat16*)p_c1l,
        (const __nv_bfloat16*)p_w1h, (const __nv_bfloat16*)p_w1l,
        (const float*)p_cb1,
        (__nv_bfloat16*)p_c2h, (__nv_bfloat16*)p_c2l, nullptr);

    // 6) conv2 (mma.sync): g_c2 -> d_out (NCHW fp32)
    conv_mma_kernel<1><<<cgrid, 256, CONV_SMEM_BYTES>>>(
        (const __nv_bfloat16*)p_c2h, (const __nv_bfloat16*)p_c2l,
        (const __nv_bfloat16*)p_w2h, (const __nv_bfloat16*)p_w2l,
        (const float*)p_cb2,
        nullptr, nullptr, out);
}